// round 8
// baseline (speedup 1.0000x reference)
#include <cuda_runtime.h>
#include <cuda_bf16.h>
#include <cstdint>

// Problem constants
#define B      64
#define T      512
#define DIM    512
#define VOCAB  32000

// ---------------- device scratch (no allocation allowed) ----------------
__device__ float    g_xp [(size_t)T * B * DIM];   // [t][b][h]  67MB
__device__ float    g_hid[(size_t)T * B * DIM];   // [t][b][h]  67MB

// ---------------- packed fp32x2 FMA (Blackwell FFMA2) ----------------
__device__ __forceinline__ void fma2(unsigned long long &d,
                                     unsigned long long a,
                                     unsigned long long b) {
    asm("fma.rn.f32x2 %0, %1, %2, %0;" : "+l"(d) : "l"(a), "l"(b));
}
__device__ __forceinline__ float sum2(unsigned long long v) {
    return __uint_as_float((unsigned)v) + __uint_as_float((unsigned)(v >> 32));
}
__device__ __forceinline__ unsigned long long pack2(float a) {
    unsigned long long r;
    asm("mov.b64 %0, {%1, %1};" : "=l"(r) : "f"(a));
    return r;
}
__device__ __forceinline__ unsigned long long packab(float a, float b) {
    unsigned long long r;
    asm("mov.b64 %0, {%1, %2};" : "=l"(r) : "f"(a), "f"(b));
    return r;
}
__device__ __forceinline__ float lo32(unsigned long long v) {
    return __uint_as_float((unsigned)v);
}
__device__ __forceinline__ float hi32(unsigned long long v) {
    return __uint_as_float((unsigned)(v >> 32));
}
__device__ __forceinline__ unsigned smem_u32(const void* p) {
    unsigned a;
    asm("{ .reg .u64 t; cvta.to.shared.u64 t, %1; cvt.u32.u64 %0, t; }"
        : "=r"(a) : "l"(p));
    return a;
}
__device__ __forceinline__ unsigned mapa_u32(unsigned a, unsigned rank) {
    unsigned d;
    asm("mapa.shared::cluster.u32 %0, %1, %2;" : "=r"(d) : "r"(a), "r"(rank));
    return d;
}
__device__ __forceinline__ void mbar_init(unsigned addr, unsigned count) {
    asm volatile("mbarrier.init.shared.b64 [%0], %1;" :: "r"(addr), "r"(count) : "memory");
}
__device__ __forceinline__ void mbar_expect(unsigned addr, unsigned bytes) {
    asm volatile("mbarrier.arrive.expect_tx.shared.b64 _, [%0], %1;"
                 :: "r"(addr), "r"(bytes) : "memory");
}
__device__ __forceinline__ void mbar_wait_cluster(unsigned addr, unsigned parity) {
    asm volatile(
        "{\n\t.reg .pred P;\n\t"
        "LW_%=:\n\t"
        "mbarrier.try_wait.parity.acquire.cluster.shared::cta.b64 P, [%0], %1, 0x989680;\n\t"
        "@P bra LD_%=;\n\t"
        "bra LW_%=;\n\t"
        "LD_%=:\n\t}"
        :: "r"(addr), "r"(parity) : "memory");
}
__device__ __forceinline__ void st_async_b64(unsigned raddr, unsigned long long v,
                                             unsigned rmbar) {
    asm volatile(
        "st.async.shared::cluster.mbarrier::complete_tx::bytes.b64 [%0], %1, [%2];"
        :: "r"(raddr), "l"(v), "r"(rmbar) : "memory");
}

// =====================================================================
// Kernel 1: xp[t][b][h] = emb[x[b][t]] . W_ih[h] + b_ih[h] + b_hh[h]
// 128x128x16 tiles, 256 threads, 8x8 register blocking, f32x2 accumulate,
// double-buffered smem (1 sync per K-tile, LDG overlapped with compute).
// =====================================================================
#define GBM 128
#define GBN 128
#define GBK 16
#define GLD 132

__global__ __launch_bounds__(256) void gemm_xp_kernel(
    const int* __restrict__ x, const float* __restrict__ emb,
    const float* __restrict__ W_ih, const float* __restrict__ b_ih,
    const float* __restrict__ b_hh)
{
    __shared__ float As[2][GBK][GLD];
    __shared__ float Bs[2][GBK][GLD];
    __shared__ int   idxs[GBM];
    __shared__ float bias[GBN];

    const int tid = threadIdx.x;
    const int tx = tid & 15, ty = tid >> 4;
    const int m0 = blockIdx.y * GBM;
    const int n0 = blockIdx.x * GBN;

    if (tid < GBM) {
        int m = m0 + tid;
        int bb = m & 63, tt = m >> 6;
        idxs[tid] = x[bb * T + tt];
        bias[tid] = b_ih[n0 + tid] + b_hh[n0 + tid];
    }
    __syncthreads();

    unsigned long long acc[8][4];
#pragma unroll
    for (int i = 0; i < 8; ++i)
#pragma unroll
        for (int j = 0; j < 4; ++j) acc[i][j] = 0ull;

    const float4* emb4 = reinterpret_cast<const float4*>(emb);
    const float4* wih4 = reinterpret_cast<const float4*>(W_ih);

    int mmv[2], kqv[2];
#pragma unroll
    for (int r = 0; r < 2; ++r) {
        int f = r * 256 + tid;
        mmv[r] = f >> 2; kqv[r] = f & 3;
    }

    float4 av[2], bv[2];
#pragma unroll
    for (int r = 0; r < 2; ++r) {
        av[r] = __ldg(&emb4[(size_t)idxs[mmv[r]] * (DIM / 4) + kqv[r]]);
        bv[r] = __ldg(&wih4[(size_t)(n0 + mmv[r]) * (DIM / 4) + kqv[r]]);
    }
#pragma unroll
    for (int r = 0; r < 2; ++r) {
        int mm = mmv[r], kc = kqv[r] * 4;
        As[0][kc + 0][mm] = av[r].x; As[0][kc + 1][mm] = av[r].y;
        As[0][kc + 2][mm] = av[r].z; As[0][kc + 3][mm] = av[r].w;
        Bs[0][kc + 0][mm] = bv[r].x; Bs[0][kc + 1][mm] = bv[r].y;
        Bs[0][kc + 2][mm] = bv[r].z; Bs[0][kc + 3][mm] = bv[r].w;
    }
    __syncthreads();

    const int NT = DIM / GBK;
    for (int kt = 0; kt < NT; ++kt) {
        const int cur = kt & 1;
        if (kt < NT - 1) {
            int kq = (kt + 1) * 4;
#pragma unroll
            for (int r = 0; r < 2; ++r) {
                av[r] = __ldg(&emb4[(size_t)idxs[mmv[r]] * (DIM / 4) + kq + kqv[r]]);
                bv[r] = __ldg(&wih4[(size_t)(n0 + mmv[r]) * (DIM / 4) + kq + kqv[r]]);
            }
        }

#pragma unroll
        for (int kk = 0; kk < GBK; ++kk) {
            float4 a0 = *reinterpret_cast<const float4*>(&As[cur][kk][ty * 4]);
            float4 a1 = *reinterpret_cast<const float4*>(&As[cur][kk][64 + ty * 4]);
            float4 b0 = *reinterpret_cast<const float4*>(&Bs[cur][kk][tx * 4]);
            float4 b1 = *reinterpret_cast<const float4*>(&Bs[cur][kk][64 + tx * 4]);
            ulonglong2 bp0 = *reinterpret_cast<ulonglong2*>(&b0);
            ulonglong2 bp1 = *reinterpret_cast<ulonglong2*>(&b1);
            float avv[8] = {a0.x, a0.y, a0.z, a0.w, a1.x, a1.y, a1.z, a1.w};
#pragma unroll
            for (int i = 0; i < 8; ++i) {
                unsigned long long ap = pack2(avv[i]);
                fma2(acc[i][0], ap, bp0.x);
                fma2(acc[i][1], ap, bp0.y);
                fma2(acc[i][2], ap, bp1.x);
                fma2(acc[i][3], ap, bp1.y);
            }
        }

        if (kt < NT - 1) {
            const int nxt = 1 - cur;
#pragma unroll
            for (int r = 0; r < 2; ++r) {
                int mm = mmv[r], kc = kqv[r] * 4;
                As[nxt][kc + 0][mm] = av[r].x; As[nxt][kc + 1][mm] = av[r].y;
                As[nxt][kc + 2][mm] = av[r].z; As[nxt][kc + 3][mm] = av[r].w;
                Bs[nxt][kc + 0][mm] = bv[r].x; Bs[nxt][kc + 1][mm] = bv[r].y;
                Bs[nxt][kc + 2][mm] = bv[r].z; Bs[nxt][kc + 3][mm] = bv[r].w;
            }
            __syncthreads();
        }
    }

    float4 bs0 = *reinterpret_cast<const float4*>(&bias[tx * 4]);
    float4 bs1 = *reinterpret_cast<const float4*>(&bias[64 + tx * 4]);
#pragma unroll
    for (int i = 0; i < 8; ++i) {
        int m = m0 + ((i < 4) ? (ty * 4 + i) : (64 + ty * 4 + (i - 4)));
        float4 o0, o1;
        o0.x = lo32(acc[i][0]) + bs0.x;  o0.y = hi32(acc[i][0]) + bs0.y;
        o0.z = lo32(acc[i][1]) + bs0.z;  o0.w = hi32(acc[i][1]) + bs0.w;
        o1.x = lo32(acc[i][2]) + bs1.x;  o1.y = hi32(acc[i][2]) + bs1.y;
        o1.z = lo32(acc[i][3]) + bs1.z;  o1.w = hi32(acc[i][3]) + bs1.w;
        *reinterpret_cast<float4*>(&g_xp[(size_t)m * DIM + n0 + tx * 4])      = o0;
        *reinterpret_cast<float4*>(&g_xp[(size_t)m * DIM + n0 + 64 + tx * 4]) = o1;
    }
}

// =====================================================================
// Kernel 2: persistent RNN recurrence over 8-CTA CLUSTERS with DSMEM
// h exchange (st.async push + mbarrier), no L2 on the critical path.
// Grid: x=8 slices (cluster), y=16 groups. 512 threads/CTA.
// Thread (h=tid&63, js=tid>>6) owns W_hh[hs0+h][js*64..+64) in 32 f32x2
// registers. mbar[buf][src_slice] expects 1KB from producer src_slice;
// each js-group waits only mbar[cur][js] -> skew-tolerant start.
// =====================================================================
#define RNN_GROUPS 16
#define RNN_SLICES 8

__global__ __launch_bounds__(512, 1) __cluster_dims__(RNN_SLICES, 1, 1)
void rnn_kernel(const float* __restrict__ W_hh)
{
    __shared__ float hsm[2][4 * DIM];                      // 16KB double-buffered h
    __shared__ float part[8 * 4 * 64];                     // 8KB [js][b][h]
    __shared__ __align__(8) unsigned long long mbar[16];   // [buf*8 + src_slice]

    const int tid   = threadIdx.x;
    const int slice = blockIdx.x;       // == cluster rank (gridDim.x == cluster)
    const int g     = blockIdx.y;
    const int hs0   = slice * 64;
    const int b0    = g * 4;
    const int h     = tid & 63;
    const int js    = tid >> 6;         // 0..7, warp-uniform
    const int ob    = js & 3;           // output batch for tid<256

    // --- W segment in registers: 64 floats = 32 f32x2 ---
    unsigned long long w[32];
    {
        const float4* Wg4 = reinterpret_cast<const float4*>(W_hh)
                            + (size_t)(hs0 + h) * (DIM / 4) + js * 16;
#pragma unroll
        for (int k = 0; k < 16; ++k) {
            float4 v = __ldg(&Wg4[k]);
            ulonglong2 p = *reinterpret_cast<ulonglong2*>(&v);
            w[2 * k]     = p.x;
            w[2 * k + 1] = p.y;
        }
    }

    // h(0) = 0
#pragma unroll
    for (int r = 0; r < 4; ++r) hsm[0][r * 512 + tid] = 0.0f;

    const unsigned hsm_base  = smem_u32(hsm);
    const unsigned mbar_base = smem_u32(mbar);

    if (tid == 0) {
#pragma unroll
        for (int i = 0; i < 16; ++i) mbar_init(mbar_base + i * 8, 1);
    }
    __syncthreads();
    if (tid < 8) {
        // initial expect posts: phase 0 of both buffers, all 8 sub-barriers
        mbar_expect(mbar_base + tid * 8, 1024);        // buf 0
        mbar_expect(mbar_base + (8 + tid) * 8, 1024);  // buf 1
    }
    asm volatile("barrier.cluster.arrive.aligned;" ::: "memory");
    asm volatile("barrier.cluster.wait.aligned;"   ::: "memory");

    // remote bases for my 4 target ranks (pair split: even h -> 0..3, odd -> 4..7)
    unsigned rem_h[4], rem_m[4];
    {
        const int rb = (h & 1) * 4;
#pragma unroll
        for (int r = 0; r < 4; ++r) {
            rem_h[r] = mapa_u32(hsm_base,  (unsigned)(rb + r));
            rem_m[r] = mapa_u32(mbar_base, (unsigned)(rb + r));
        }
    }

    int ph0 = 0, ph1 = 0;
    const int cbK = js * 16;
    float hid_keep = 0.0f;

    for (int t = 0; t < T; ++t) {
        const int cur = t & 1;

        // prefetch xp (L2/DRAM latency hidden behind wait+matvec)
        float xpv = 0.0f;
        if (tid < 256)
            xpv = __ldg(&g_xp[((size_t)t * B + (b0 + ob)) * DIM + hs0 + h]);

        // ---- per-js gate: wait ONLY producer js's 1KB sub-barrier ----
        if (t > 0) {
            unsigned ma = mbar_base + (unsigned)((cur * 8 + js) * 8);
            int p = cur ? ph1 : ph0;
            mbar_wait_cluster(ma, (unsigned)p);
            if (h == 0 && t + 2 < T)      // repost for this barrier's next phase
                mbar_expect(ma, 1024);
            if (cur) ph1 ^= 1; else ph0 ^= 1;
        }

        // ---- matvec: W regs x H broadcast-LDS ----
        const ulonglong2* H2 = reinterpret_cast<const ulonglong2*>(hsm[cur]);
        unsigned long long a0x=0,a0y=0,a1x=0,a1y=0,a2x=0,a2y=0,a3x=0,a3y=0;
#pragma unroll
        for (int k = 0; k < 16; ++k) {
            int c = cbK + k;
            ulonglong2 x0 = H2[c];
            fma2(a0x, w[2*k], x0.x); fma2(a0y, w[2*k+1], x0.y);
            ulonglong2 x1 = H2[128 + c];
            fma2(a1x, w[2*k], x1.x); fma2(a1y, w[2*k+1], x1.y);
            ulonglong2 x2 = H2[256 + c];
            fma2(a2x, w[2*k], x2.x); fma2(a2y, w[2*k+1], x2.y);
            ulonglong2 x3 = H2[384 + c];
            fma2(a3x, w[2*k], x3.x); fma2(a3y, w[2*k+1], x3.y);
        }
        part[(js * 4 + 0) * 64 + h] = sum2(a0x) + sum2(a0y);
        part[(js * 4 + 1) * 64 + h] = sum2(a1x) + sum2(a1y);
        part[(js * 4 + 2) * 64 + h] = sum2(a2x) + sum2(a2y);
        part[(js * 4 + 3) * 64 + h] = sum2(a3x) + sum2(a3y);
        __syncthreads();

        // ---- reduce, tanh, DSMEM push to all 8 cluster CTAs ----
        if (tid < 256) {
            float dot = 0.0f;
#pragma unroll
            for (int s = 0; s < 8; ++s) dot += part[(s * 4 + ob) * 64 + h];
            float hn = tanhf(dot + xpv);
            hid_keep = hn;
            if (t < T - 1) {
                const int nxt = (t + 1) & 1;
                float ov = __shfl_xor_sync(0xffffffffu, hn, 1);
                unsigned long long pk = ((h & 1) == 0) ? packab(hn, ov)
                                                       : packab(ov, hn);
                unsigned off  = (unsigned)((nxt * 2048 + ob * 512 + hs0 + (h & ~1)) * 4);
                unsigned moff = (unsigned)((nxt * 8 + slice) * 8);
#pragma unroll
                for (int r = 0; r < 4; ++r)
                    st_async_b64(rem_h[r] + off, pk, rem_m[r] + moff);
            }
        }
        __syncthreads();   // part WAR guard across steps

        // ---- lazy history store (off the critical exchange path) ----
        if (tid < 256)
            g_hid[((size_t)t * B + (b0 + ob)) * DIM + hs0 + h] = hid_keep;
    }
}

// =====================================================================
// Kernel 3: softmax over H (axis=1 of [B,H,T]) + transpose -> [b][h][t]
// =====================================================================
__global__ __launch_bounds__(256) void softmax_kernel(float* __restrict__ out)
{
    __shared__ float tile[16][513];
    __shared__ float rinv[16];

    const int tid = threadIdx.x;
    const int bb  = blockIdx.y;
    const int t0  = blockIdx.x * 16;

#pragma unroll
    for (int it = 0; it < 32; ++it) {
        int f = it * 256 + tid;
        int tt = f >> 9, hh = f & 511;
        tile[tt][hh] = __ldg(&g_hid[((size_t)(t0 + tt) * B + bb) * DIM + hh]);
    }
    __syncthreads();

    const int wid = tid >> 5, lane = tid & 31;
#pragma unroll
    for (int rr = 0; rr < 2; ++rr) {
        int tt = wid * 2 + rr;
        float m = -3.4e38f;
#pragma unroll
        for (int k = 0; k < 16; ++k) m = fmaxf(m, tile[tt][lane + 32 * k]);
#pragma unroll
        for (int off = 16; off >= 1; off >>= 1)
            m = fmaxf(m, __shfl_xor_sync(0xffffffffu, m, off));
        float s = 0.0f;
#pragma unroll
        for (int k = 0; k < 16; ++k) {
            float e = __expf(tile[tt][lane + 32 * k] - m);
            tile[tt][lane + 32 * k] = e;
            s += e;
        }
#pragma unroll
        for (int off = 16; off >= 1; off >>= 1)
            s += __shfl_xor_sync(0xffffffffu, s, off);
        if (lane == 0) rinv[tt] = 1.0f / s;
    }
    __syncthreads();

    const int hw  = tid >> 4;
    const int l16 = tid & 15;
#pragma unroll
    for (int it = 0; it < 32; ++it) {
        int hh = it * 16 + hw;
        float v = tile[l16][hh] * rinv[l16];
        out[((size_t)bb * DIM + hh) * T + t0 + l16] = v;
    }
}

// =====================================================================
extern "C" void kernel_launch(void* const* d_in, const int* in_sizes, int n_in,
                              void* d_out, int out_size)
{
    const int*   x    = (const int*)  d_in[0];
    const float* emb  = (const float*)d_in[1];
    const float* W_ih = (const float*)d_in[2];
    const float* W_hh = (const float*)d_in[3];
    const float* b_ih = (const float*)d_in[4];
    const float* b_hh = (const float*)d_in[5];
    float* out = (float*)d_out;

    // 1) input projection GEMM -> g_xp
    gemm_xp_kernel<<<dim3(DIM / GBN, (T * B) / GBM), 256>>>(x, emb, W_ih, b_ih, b_hh);

    // 2) persistent recurrence (16 clusters of 8 CTAs) -> g_hid
    rnn_kernel<<<dim3(RNN_SLICES, RNN_GROUPS), 512>>>(W_hh);

    // 3) softmax over H + transpose -> out
    softmax_kernel<<<dim3(T / 16, B), 256>>>(out);
}

// round 10
// speedup vs baseline: 1.0248x; 1.0248x over previous
#include <cuda_runtime.h>
#include <cuda_bf16.h>
#include <cstdint>

// Problem constants
#define B      64
#define T      512
#define DIM    512
#define VOCAB  32000

// ---------------- device scratch (no allocation allowed) ----------------
__device__ float    g_xp  [(size_t)T * B * DIM];   // [t][b][h]  67MB
__device__ float    g_hid [(size_t)T * B * DIM];   // [t][b][h]  67MB
__device__ float    g_hbuf[2 * B * DIM];           // double-buffered h state
__device__ unsigned g_flag[(size_t)T * 2 * 8 * 16 * 8];  // (t,phase,slice,g) x8 stride

// ---------------- packed fp32x2 FMA (Blackwell FFMA2) ----------------
__device__ __forceinline__ void fma2(unsigned long long &d,
                                     unsigned long long a,
                                     unsigned long long b) {
    asm("fma.rn.f32x2 %0, %1, %2, %0;" : "+l"(d) : "l"(a), "l"(b));
}
__device__ __forceinline__ float sum2(unsigned long long v) {
    return __uint_as_float((unsigned)v) + __uint_as_float((unsigned)(v >> 32));
}
__device__ __forceinline__ unsigned long long pack2(float a) {
    unsigned long long r;
    asm("mov.b64 %0, {%1, %1};" : "=l"(r) : "f"(a));
    return r;
}
__device__ __forceinline__ float lo32(unsigned long long v) {
    return __uint_as_float((unsigned)v);
}
__device__ __forceinline__ float hi32(unsigned long long v) {
    return __uint_as_float((unsigned)(v >> 32));
}

// =====================================================================
// Kernel 1: xp[t][b][h] = emb[x[b][t]] . W_ih[h] + b_ih[h] + b_hh[h]
// 128x128x16 tiles, 256 threads, 8x8 register blocking, f32x2 accumulate,
// double-buffered smem (1 sync per K-tile, LDG overlapped with compute).
// =====================================================================
#define GBM 128
#define GBN 128
#define GBK 16
#define GLD 132

__global__ __launch_bounds__(256) void gemm_xp_kernel(
    const int* __restrict__ x, const float* __restrict__ emb,
    const float* __restrict__ W_ih, const float* __restrict__ b_ih,
    const float* __restrict__ b_hh)
{
    __shared__ float As[2][GBK][GLD];
    __shared__ float Bs[2][GBK][GLD];
    __shared__ int   idxs[GBM];
    __shared__ float bias[GBN];

    const int tid = threadIdx.x;
    const int tx = tid & 15, ty = tid >> 4;
    const int m0 = blockIdx.y * GBM;
    const int n0 = blockIdx.x * GBN;

    if (tid < GBM) {
        int m = m0 + tid;
        int bb = m & 63, tt = m >> 6;
        idxs[tid] = x[bb * T + tt];
        bias[tid] = b_ih[n0 + tid] + b_hh[n0 + tid];
    }
    __syncthreads();

    unsigned long long acc[8][4];
#pragma unroll
    for (int i = 0; i < 8; ++i)
#pragma unroll
        for (int j = 0; j < 4; ++j) acc[i][j] = 0ull;

    const float4* emb4 = reinterpret_cast<const float4*>(emb);
    const float4* wih4 = reinterpret_cast<const float4*>(W_ih);

    int mmv[2], kqv[2];
#pragma unroll
    for (int r = 0; r < 2; ++r) {
        int f = r * 256 + tid;
        mmv[r] = f >> 2; kqv[r] = f & 3;
    }

    float4 av[2], bv[2];
#pragma unroll
    for (int r = 0; r < 2; ++r) {
        av[r] = __ldg(&emb4[(size_t)idxs[mmv[r]] * (DIM / 4) + kqv[r]]);
        bv[r] = __ldg(&wih4[(size_t)(n0 + mmv[r]) * (DIM / 4) + kqv[r]]);
    }
#pragma unroll
    for (int r = 0; r < 2; ++r) {
        int mm = mmv[r], kc = kqv[r] * 4;
        As[0][kc + 0][mm] = av[r].x; As[0][kc + 1][mm] = av[r].y;
        As[0][kc + 2][mm] = av[r].z; As[0][kc + 3][mm] = av[r].w;
        Bs[0][kc + 0][mm] = bv[r].x; Bs[0][kc + 1][mm] = bv[r].y;
        Bs[0][kc + 2][mm] = bv[r].z; Bs[0][kc + 3][mm] = bv[r].w;
    }
    __syncthreads();

    const int NT = DIM / GBK;
    for (int kt = 0; kt < NT; ++kt) {
        const int cur = kt & 1;
        if (kt < NT - 1) {
            int kq = (kt + 1) * 4;
#pragma unroll
            for (int r = 0; r < 2; ++r) {
                av[r] = __ldg(&emb4[(size_t)idxs[mmv[r]] * (DIM / 4) + kq + kqv[r]]);
                bv[r] = __ldg(&wih4[(size_t)(n0 + mmv[r]) * (DIM / 4) + kq + kqv[r]]);
            }
        }

#pragma unroll
        for (int kk = 0; kk < GBK; ++kk) {
            float4 a0 = *reinterpret_cast<const float4*>(&As[cur][kk][ty * 4]);
            float4 a1 = *reinterpret_cast<const float4*>(&As[cur][kk][64 + ty * 4]);
            float4 b0 = *reinterpret_cast<const float4*>(&Bs[cur][kk][tx * 4]);
            float4 b1 = *reinterpret_cast<const float4*>(&Bs[cur][kk][64 + tx * 4]);
            ulonglong2 bp0 = *reinterpret_cast<ulonglong2*>(&b0);
            ulonglong2 bp1 = *reinterpret_cast<ulonglong2*>(&b1);
            float avv[8] = {a0.x, a0.y, a0.z, a0.w, a1.x, a1.y, a1.z, a1.w};
#pragma unroll
            for (int i = 0; i < 8; ++i) {
                unsigned long long ap = pack2(avv[i]);
                fma2(acc[i][0], ap, bp0.x);
                fma2(acc[i][1], ap, bp0.y);
                fma2(acc[i][2], ap, bp1.x);
                fma2(acc[i][3], ap, bp1.y);
            }
        }

        if (kt < NT - 1) {
            const int nxt = 1 - cur;
#pragma unroll
            for (int r = 0; r < 2; ++r) {
                int mm = mmv[r], kc = kqv[r] * 4;
                As[nxt][kc + 0][mm] = av[r].x; As[nxt][kc + 1][mm] = av[r].y;
                As[nxt][kc + 2][mm] = av[r].z; As[nxt][kc + 3][mm] = av[r].w;
                Bs[nxt][kc + 0][mm] = bv[r].x; Bs[nxt][kc + 1][mm] = bv[r].y;
                Bs[nxt][kc + 2][mm] = bv[r].z; Bs[nxt][kc + 3][mm] = bv[r].w;
            }
            __syncthreads();
        }
    }

    float4 bs0 = *reinterpret_cast<const float4*>(&bias[tx * 4]);
    float4 bs1 = *reinterpret_cast<const float4*>(&bias[64 + tx * 4]);
#pragma unroll
    for (int i = 0; i < 8; ++i) {
        int m = m0 + ((i < 4) ? (ty * 4 + i) : (64 + ty * 4 + (i - 4)));
        float4 o0, o1;
        o0.x = lo32(acc[i][0]) + bs0.x;  o0.y = hi32(acc[i][0]) + bs0.y;
        o0.z = lo32(acc[i][1]) + bs0.z;  o0.w = hi32(acc[i][1]) + bs0.w;
        o1.x = lo32(acc[i][2]) + bs1.x;  o1.y = hi32(acc[i][2]) + bs1.y;
        o1.z = lo32(acc[i][3]) + bs1.z;  o1.w = hi32(acc[i][3]) + bs1.w;
        *reinterpret_cast<float4*>(&g_xp[(size_t)m * DIM + n0 + tx * 4])      = o0;
        *reinterpret_cast<float4*>(&g_xp[(size_t)m * DIM + n0 + 64 + tx * 4]) = o1;
    }
}

// =====================================================================
// Kernel 2: persistent RNN, TWO-PHASE batch pipelining.
// Grid: (8 slices, 16 groups) = 128 co-resident CTAs, 512 threads.
// Each CTA's 4 batches split into phase 0 (b0,b0+1) and phase 1 (b0+2,
// b0+3) — independent recurrences sharing the W registers. Phase u's
// inter-CTA exchange (R7's proven release/acquire flag protocol) has a
// half-step of slack filled by the other phase's matvec.
// Thread (h=tid&63, js=tid>>6) owns W_hh[hs0+h][js*64..+64) in 32 f32x2
// registers; each js-group gates on its producer slice's per-phase flag.
// =====================================================================
#define RNN_GROUPS 16
#define RNN_SLICES 8

__device__ __forceinline__ unsigned flag_off(int t, int u, int s, int g) {
    return (unsigned)((((t * 2 + u) * 8 + s) * 16 + g) * 8);
}

__global__ __launch_bounds__(512, 1) void rnn_kernel(const float* __restrict__ W_hh)
{
    __shared__ float hsm[2][2][DIM];        // [phase][local batch][col] 8KB
    __shared__ float part[2][8 * 2 * 64];   // [phase][js][bi][h] 8KB

    const int tid   = threadIdx.x;
    const int slice = blockIdx.x;
    const int g     = blockIdx.y;
    const int hs0   = slice * 64;
    const int b0    = g * 4;
    const int h     = tid & 63;
    const int js    = tid >> 6;      // 0..7, warp-uniform

    // --- this thread's W segment: 64 floats = 32 f32x2 regs ---
    unsigned long long w[32];
    {
        const float4* Wg4 = reinterpret_cast<const float4*>(W_hh)
                            + (size_t)(hs0 + h) * (DIM / 4) + js * 16;
#pragma unroll
        for (int k = 0; k < 16; ++k) {
            float4 v = __ldg(&Wg4[k]);
            ulonglong2 p = *reinterpret_cast<ulonglong2*>(&v);
            w[2 * k]     = p.x;
            w[2 * k + 1] = p.y;
        }
    }

    // h(0) = 0 for both phases
    {
        float* hf = (float*)hsm;
#pragma unroll
        for (int r = 0; r < 4; ++r) hf[r * 512 + tid] = 0.0f;
    }
    __syncthreads();

    // loader coords (h < 32): lb = local batch, lc = float offset in slice
    const int lb = h >> 4;          // 0..1
    const int lc = (h & 15) * 4;

    for (int t = 0; t < T; ++t) {
        // ---- prefetch xp for both phases (DRAM latency hidden) ----
        float xp0 = 0.0f, xp1 = 0.0f;
        if (tid < 128) {
            int bi = tid >> 6;
            xp0 = __ldg(&g_xp[((size_t)t * B + b0 + bi)     * DIM + hs0 + h]);
            xp1 = __ldg(&g_xp[((size_t)t * B + b0 + 2 + bi) * DIM + hs0 + h]);
        }

#pragma unroll
        for (int u = 0; u < 2; ++u) {
            // ---- per-js gate: wait producer slice js's phase-u flag ----
            if (t > 0) {
                const unsigned* fp = &g_flag[flag_off(t, u, js, g)];
                unsigned v;
                do {
                    asm volatile("ld.acquire.gpu.global.u32 %0, [%1];"
                                 : "=r"(v) : "l"(fp) : "memory");
                } while (!v);
                if (h < 32) {
                    const float4* src = reinterpret_cast<const float4*>(
                        &g_hbuf[(size_t)(t & 1) * B * DIM
                                + (size_t)(b0 + 2 * u + lb) * DIM + js * 64 + lc]);
                    float4 hv = __ldcg(src);
                    *reinterpret_cast<float4*>(&hsm[u][lb][js * 64 + lc]) = hv;
                }
                asm volatile("bar.sync %0, %1;" :: "r"(js + 1), "r"(64) : "memory");
            }

            // ---- matvec phase u: W regs x H broadcast-LDS (2 batches) ----
            const ulonglong2* H0 = reinterpret_cast<const ulonglong2*>(hsm[u][0]);
            const ulonglong2* H1 = reinterpret_cast<const ulonglong2*>(hsm[u][1]);
            unsigned long long a0x=0, a0y=0, a1x=0, a1y=0;
#pragma unroll
            for (int k = 0; k < 16; ++k) {
                int c = js * 16 + k;
                ulonglong2 x0 = H0[c];
                fma2(a0x, w[2*k], x0.x); fma2(a0y, w[2*k+1], x0.y);
                ulonglong2 x1 = H1[c];
                fma2(a1x, w[2*k], x1.x); fma2(a1y, w[2*k+1], x1.y);
            }
            part[u][(js * 2 + 0) * 64 + h] = sum2(a0x) + sum2(a0y);
            part[u][(js * 2 + 1) * 64 + h] = sum2(a1x) + sum2(a1y);
            __syncthreads();

            // ---- reduce phase u (tid<128), store h, release flag ----
            if (tid < 128) {
                int bi = tid >> 6;
                float dot = 0.0f;
#pragma unroll
                for (int s = 0; s < 8; ++s) dot += part[u][(s * 2 + bi) * 64 + h];
                float hn = tanhf(dot + (u ? xp1 : xp0));
                int b = b0 + 2 * u + bi;
                if (t < T - 1)
                    g_hbuf[(size_t)((t + 1) & 1) * B * DIM
                           + (size_t)b * DIM + hs0 + h] = hn;
                // join the 128 writer threads, then one release (h-b trans.)
                asm volatile("bar.sync 10, 128;" ::: "memory");
                if (tid == 0 && t < T - 1) {
                    unsigned* fp = &g_flag[flag_off(t + 1, u, slice, g)];
                    asm volatile("st.release.gpu.global.u32 [%0], %1;"
                                 :: "l"(fp), "r"(1u) : "memory");
                }
                // lazy history store (off the critical path)
                g_hid[((size_t)t * B + b) * DIM + hs0 + h] = hn;
            }
        }
    }
}

// =====================================================================
// Kernel 3: softmax over H (axis=1 of [B,H,T]) + transpose -> [b][h][t]
// =====================================================================
__global__ __launch_bounds__(256) void softmax_kernel(float* __restrict__ out)
{
    __shared__ float tile[16][513];
    __shared__ float rinv[16];

    const int tid = threadIdx.x;
    const int bb  = blockIdx.y;
    const int t0  = blockIdx.x * 16;

#pragma unroll
    for (int it = 0; it < 32; ++it) {
        int f = it * 256 + tid;
        int tt = f >> 9, hh = f & 511;
        tile[tt][hh] = __ldg(&g_hid[((size_t)(t0 + tt) * B + bb) * DIM + hh]);
    }
    __syncthreads();

    const int wid = tid >> 5, lane = tid & 31;
#pragma unroll
    for (int rr = 0; rr < 2; ++rr) {
        int tt = wid * 2 + rr;
        float m = -3.4e38f;
#pragma unroll
        for (int k = 0; k < 16; ++k) m = fmaxf(m, tile[tt][lane + 32 * k]);
#pragma unroll
        for (int off = 16; off >= 1; off >>= 1)
            m = fmaxf(m, __shfl_xor_sync(0xffffffffu, m, off));
        float s = 0.0f;
#pragma unroll
        for (int k = 0; k < 16; ++k) {
            float e = __expf(tile[tt][lane + 32 * k] - m);
            tile[tt][lane + 32 * k] = e;
            s += e;
        }
#pragma unroll
        for (int off = 16; off >= 1; off >>= 1)
            s += __shfl_xor_sync(0xffffffffu, s, off);
        if (lane == 0) rinv[tt] = 1.0f / s;
    }
    __syncthreads();

    const int hw  = tid >> 4;
    const int l16 = tid & 15;
#pragma unroll
    for (int it = 0; it < 32; ++it) {
        int hh = it * 16 + hw;
        float v = tile[l16][hh] * rinv[l16];
        out[((size_t)bb * DIM + hh) * T + t0 + l16] = v;
    }
}

// =====================================================================
extern "C" void kernel_launch(void* const* d_in, const int* in_sizes, int n_in,
                              void* d_out, int out_size)
{
    const int*   x    = (const int*)  d_in[0];
    const float* emb  = (const float*)d_in[1];
    const float* W_ih = (const float*)d_in[2];
    const float* W_hh = (const float*)d_in[3];
    const float* b_ih = (const float*)d_in[4];
    const float* b_hh = (const float*)d_in[5];
    float* out = (float*)d_out;

    void* p_flag;
    cudaGetSymbolAddress(&p_flag, g_flag);
    cudaMemsetAsync(p_flag, 0, sizeof(unsigned) * (size_t)T * 2 * 8 * 16 * 8);

    // 1) input projection GEMM -> g_xp
    gemm_xp_kernel<<<dim3(DIM / GBN, (T * B) / GBM), 256>>>(x, emb, W_ih, b_ih, b_hh);

    // 2) persistent recurrence (two-phase pipelined) -> g_hid
    rnn_kernel<<<dim3(RNN_SLICES, RNN_GROUPS), 512>>>(W_hh);

    // 3) softmax over H + transpose -> out
    softmax_kernel<<<dim3(T / 16, B), 256>>>(out);
}

// round 11
// speedup vs baseline: 1.1974x; 1.1684x over previous
#include <cuda_runtime.h>
#include <cuda_bf16.h>
#include <cstdint>

// Problem constants
#define B      64
#define T      512
#define DIM    512
#define VOCAB  32000

// ---------------- device scratch (no allocation allowed) ----------------
__device__ float    g_xp  [(size_t)T * B * DIM];   // [t][b][h]  67MB
__device__ float    g_hid [(size_t)T * B * DIM];   // [t][b][h]  67MB
__device__ float    g_hbuf[2 * B * DIM];           // double-buffered h state
__device__ unsigned g_flag[(size_t)T * 8 * 16 * 8];  // (t,slice,g), 32B stride

// ---------------- packed fp32x2 FMA (Blackwell FFMA2) ----------------
__device__ __forceinline__ void fma2(unsigned long long &d,
                                     unsigned long long a,
                                     unsigned long long b) {
    asm("fma.rn.f32x2 %0, %1, %2, %0;" : "+l"(d) : "l"(a), "l"(b));
}
__device__ __forceinline__ float sum2(unsigned long long v) {
    return __uint_as_float((unsigned)v) + __uint_as_float((unsigned)(v >> 32));
}
__device__ __forceinline__ unsigned long long pack2(float a) {
    unsigned long long r;
    asm("mov.b64 %0, {%1, %1};" : "=l"(r) : "f"(a));
    return r;
}
__device__ __forceinline__ float lo32(unsigned long long v) {
    return __uint_as_float((unsigned)v);
}
__device__ __forceinline__ float hi32(unsigned long long v) {
    return __uint_as_float((unsigned)(v >> 32));
}

// =====================================================================
// Kernel 1: xp[t][b][h] = emb[x[b][t]] . W_ih[h] + b_ih[h] + b_hh[h]
// 128x128x16 tiles, 256 threads, 8x8 register blocking, f32x2 accumulate,
// double-buffered smem (1 sync per K-tile, LDG overlapped with compute).
// =====================================================================
#define GBM 128
#define GBN 128
#define GBK 16
#define GLD 132

__global__ __launch_bounds__(256) void gemm_xp_kernel(
    const int* __restrict__ x, const float* __restrict__ emb,
    const float* __restrict__ W_ih, const float* __restrict__ b_ih,
    const float* __restrict__ b_hh)
{
    __shared__ float As[2][GBK][GLD];
    __shared__ float Bs[2][GBK][GLD];
    __shared__ int   idxs[GBM];
    __shared__ float bias[GBN];

    const int tid = threadIdx.x;
    const int tx = tid & 15, ty = tid >> 4;
    const int m0 = blockIdx.y * GBM;
    const int n0 = blockIdx.x * GBN;

    if (tid < GBM) {
        int m = m0 + tid;
        int bb = m & 63, tt = m >> 6;
        idxs[tid] = x[bb * T + tt];
        bias[tid] = b_ih[n0 + tid] + b_hh[n0 + tid];
    }
    __syncthreads();

    unsigned long long acc[8][4];
#pragma unroll
    for (int i = 0; i < 8; ++i)
#pragma unroll
        for (int j = 0; j < 4; ++j) acc[i][j] = 0ull;

    const float4* emb4 = reinterpret_cast<const float4*>(emb);
    const float4* wih4 = reinterpret_cast<const float4*>(W_ih);

    int mmv[2], kqv[2];
#pragma unroll
    for (int r = 0; r < 2; ++r) {
        int f = r * 256 + tid;
        mmv[r] = f >> 2; kqv[r] = f & 3;
    }

    float4 av[2], bv[2];
#pragma unroll
    for (int r = 0; r < 2; ++r) {
        av[r] = __ldg(&emb4[(size_t)idxs[mmv[r]] * (DIM / 4) + kqv[r]]);
        bv[r] = __ldg(&wih4[(size_t)(n0 + mmv[r]) * (DIM / 4) + kqv[r]]);
    }
#pragma unroll
    for (int r = 0; r < 2; ++r) {
        int mm = mmv[r], kc = kqv[r] * 4;
        As[0][kc + 0][mm] = av[r].x; As[0][kc + 1][mm] = av[r].y;
        As[0][kc + 2][mm] = av[r].z; As[0][kc + 3][mm] = av[r].w;
        Bs[0][kc + 0][mm] = bv[r].x; Bs[0][kc + 1][mm] = bv[r].y;
        Bs[0][kc + 2][mm] = bv[r].z; Bs[0][kc + 3][mm] = bv[r].w;
    }
    __syncthreads();

    const int NT = DIM / GBK;
    for (int kt = 0; kt < NT; ++kt) {
        const int cur = kt & 1;
        if (kt < NT - 1) {
            int kq = (kt + 1) * 4;
#pragma unroll
            for (int r = 0; r < 2; ++r) {
                av[r] = __ldg(&emb4[(size_t)idxs[mmv[r]] * (DIM / 4) + kq + kqv[r]]);
                bv[r] = __ldg(&wih4[(size_t)(n0 + mmv[r]) * (DIM / 4) + kq + kqv[r]]);
            }
        }

#pragma unroll
        for (int kk = 0; kk < GBK; ++kk) {
            float4 a0 = *reinterpret_cast<const float4*>(&As[cur][kk][ty * 4]);
            float4 a1 = *reinterpret_cast<const float4*>(&As[cur][kk][64 + ty * 4]);
            float4 b0 = *reinterpret_cast<const float4*>(&Bs[cur][kk][tx * 4]);
            float4 b1 = *reinterpret_cast<const float4*>(&Bs[cur][kk][64 + tx * 4]);
            ulonglong2 bp0 = *reinterpret_cast<ulonglong2*>(&b0);
            ulonglong2 bp1 = *reinterpret_cast<ulonglong2*>(&b1);
            float avv[8] = {a0.x, a0.y, a0.z, a0.w, a1.x, a1.y, a1.z, a1.w};
#pragma unroll
            for (int i = 0; i < 8; ++i) {
                unsigned long long ap = pack2(avv[i]);
                fma2(acc[i][0], ap, bp0.x);
                fma2(acc[i][1], ap, bp0.y);
                fma2(acc[i][2], ap, bp1.x);
                fma2(acc[i][3], ap, bp1.y);
            }
        }

        if (kt < NT - 1) {
            const int nxt = 1 - cur;
#pragma unroll
            for (int r = 0; r < 2; ++r) {
                int mm = mmv[r], kc = kqv[r] * 4;
                As[nxt][kc + 0][mm] = av[r].x; As[nxt][kc + 1][mm] = av[r].y;
                As[nxt][kc + 2][mm] = av[r].z; As[nxt][kc + 3][mm] = av[r].w;
                Bs[nxt][kc + 0][mm] = bv[r].x; Bs[nxt][kc + 1][mm] = bv[r].y;
                Bs[nxt][kc + 2][mm] = bv[r].z; Bs[nxt][kc + 3][mm] = bv[r].w;
            }
            __syncthreads();
        }
    }

    float4 bs0 = *reinterpret_cast<const float4*>(&bias[tx * 4]);
    float4 bs1 = *reinterpret_cast<const float4*>(&bias[64 + tx * 4]);
#pragma unroll
    for (int i = 0; i < 8; ++i) {
        int m = m0 + ((i < 4) ? (ty * 4 + i) : (64 + ty * 4 + (i - 4)));
        float4 o0, o1;
        o0.x = lo32(acc[i][0]) + bs0.x;  o0.y = hi32(acc[i][0]) + bs0.y;
        o0.z = lo32(acc[i][1]) + bs0.z;  o0.w = hi32(acc[i][1]) + bs0.w;
        o1.x = lo32(acc[i][2]) + bs1.x;  o1.y = hi32(acc[i][2]) + bs1.y;
        o1.z = lo32(acc[i][3]) + bs1.z;  o1.w = hi32(acc[i][3]) + bs1.w;
        *reinterpret_cast<float4*>(&g_xp[(size_t)m * DIM + n0 + tx * 4])      = o0;
        *reinterpret_cast<float4*>(&g_xp[(size_t)m * DIM + n0 + 64 + tx * 4]) = o1;
    }
}

// =====================================================================
// Kernel 2: persistent RNN recurrence (R7 protocol, de-contended).
// Grid: (8 slices, 16 groups) = 128 co-resident CTAs, 512 threads.
// Thread (h=tid&63, js=tid>>6) owns W_hh[hs0+h][js*64..+64) in 32 f32x2
// registers. Per-js-group gate on its producer slice's per-step flag:
//   ONE thread (h==0) acquire-polls the flag   (8 pollers/flag, not 512)
//   bar.sync(js) propagates the acquire, then all 64 threads ldcg 1KB.
// part[] double-buffered by step parity -> single __syncthreads per step;
// release fires right after the join + writer-warp bar, off the tail.
// Safety: release is ordered after the full join-__syncthreads, so all
// gate-loads of step t happen-before flag(t+1); transitively, a producer
// reaches its step-t+1 g_hbuf overwrite only after every consumer's
// step-t read of that buffer completed (WAR-safe, same as R7).
// =====================================================================
#define RNN_GROUPS 16
#define RNN_SLICES 8

__device__ __forceinline__ unsigned flag_idx(int t, int s, int g) {
    return (unsigned)(((t * 8 + s) * 16 + g) * 8);
}

__global__ __launch_bounds__(512, 1) void rnn_kernel(const float* __restrict__ W_hh)
{
    __shared__ float hsm[4 * DIM];            // 8KB h state [b][col] (group-private slices)
    __shared__ float part[2][8 * 4 * 64];     // 16KB [parity][js][b][h]

    const int tid   = threadIdx.x;
    const int slice = blockIdx.x;
    const int g     = blockIdx.y;
    const int hs0   = slice * 64;
    const int b0    = g * 4;
    const int h     = tid & 63;
    const int js    = tid >> 6;      // 0..7, warp-uniform
    const int ob    = js & 3;        // output batch for tid<256

    // --- this thread's W segment: 64 floats = 32 f32x2 regs ---
    unsigned long long w[32];
    {
        const float4* Wg4 = reinterpret_cast<const float4*>(W_hh)
                            + (size_t)(hs0 + h) * (DIM / 4) + js * 16;
#pragma unroll
        for (int k = 0; k < 16; ++k) {
            float4 v = __ldg(&Wg4[k]);
            ulonglong2 p = *reinterpret_cast<ulonglong2*>(&v);
            w[2 * k]     = p.x;
            w[2 * k + 1] = p.y;
        }
    }

    // h(0) = 0
#pragma unroll
    for (int r = 0; r < 4; ++r) hsm[r * 512 + tid] = 0.0f;

    // per-js slice-load coords: 64 threads x float4 = 1KB slice
    const int lb  = h >> 4;          // batch 0..3
    const int lc  = (h & 15) * 4;    // float offset within 64-col slice
    const int cbK = js * 16;         // ulonglong2 column base

    __syncthreads();

    for (int t = 0; t < T; ++t) {
        const int cur = t & 1;

        // ---- prefetch xp (DRAM latency hidden behind gate+matvec) ----
        float xpv = 0.0f;
        if (tid < 256)
            xpv = __ldg(&g_xp[((size_t)t * B + (b0 + ob)) * DIM + hs0 + h]);

        // ---- per-js gate: lane-0 acquire-poll, then group-wide load ----
        if (t > 0) {
            if (h == 0) {
                const unsigned* fp = &g_flag[flag_idx(t, js, g)];
                unsigned v;
                do {
                    asm volatile("ld.acquire.gpu.global.u32 %0, [%1];"
                                 : "=r"(v) : "l"(fp) : "memory");
                } while (!v);
            }
            asm volatile("bar.sync %0, %1;" :: "r"(js + 1), "r"(64) : "memory");
            const float4* src = reinterpret_cast<const float4*>(
                &g_hbuf[(size_t)cur * B * DIM
                        + (size_t)(b0 + lb) * DIM + js * 64 + lc]);
            float4 hv = __ldcg(src);
            *reinterpret_cast<float4*>(&hsm[lb * 512 + js * 64 + lc]) = hv;
            asm volatile("bar.sync %0, %1;" :: "r"(js + 1), "r"(64) : "memory");
        }

        // ---- matvec: W from registers, H via broadcast LDS ----
        const ulonglong2* H2 = reinterpret_cast<const ulonglong2*>(hsm);
        unsigned long long a0x=0,a0y=0,a1x=0,a1y=0,a2x=0,a2y=0,a3x=0,a3y=0;
#pragma unroll
        for (int k = 0; k < 16; ++k) {
            int c = cbK + k;
            ulonglong2 x0 = H2[c];
            fma2(a0x, w[2*k], x0.x); fma2(a0y, w[2*k+1], x0.y);
            ulonglong2 x1 = H2[128 + c];
            fma2(a1x, w[2*k], x1.x); fma2(a1y, w[2*k+1], x1.y);
            ulonglong2 x2 = H2[256 + c];
            fma2(a2x, w[2*k], x2.x); fma2(a2y, w[2*k+1], x2.y);
            ulonglong2 x3 = H2[384 + c];
            fma2(a3x, w[2*k], x3.x); fma2(a3y, w[2*k+1], x3.y);
        }
        part[cur][(js * 4 + 0) * 64 + h] = sum2(a0x) + sum2(a0y);
        part[cur][(js * 4 + 1) * 64 + h] = sum2(a1x) + sum2(a1y);
        part[cur][(js * 4 + 2) * 64 + h] = sum2(a2x) + sum2(a2y);
        part[cur][(js * 4 + 3) * 64 + h] = sum2(a3x) + sum2(a3y);
        __syncthreads();     // join: all part[cur] visible; bounds skew to 1 step

        // ---- reduce 8 partials, add xp, tanh, publish, release ----
        if (tid < 256) {
            float dot = 0.0f;
#pragma unroll
            for (int s = 0; s < 8; ++s) dot += part[cur][(s * 4 + ob) * 64 + h];
            float hn = tanhf(dot + xpv);
            if (t < T - 1)
                g_hbuf[(size_t)((t + 1) & 1) * B * DIM
                       + (size_t)(b0 + ob) * DIM + hs0 + h] = hn;
            asm volatile("bar.sync 9, 256;" ::: "memory");   // writer-warps join
            if (tid == 0 && t < T - 1) {
                unsigned* fp = &g_flag[flag_idx(t + 1, slice, g)];
                asm volatile("st.release.gpu.global.u32 [%0], %1;"
                             :: "l"(fp), "r"(1u) : "memory");
            }
            // lazy history store (off the critical exchange path)
            g_hid[((size_t)t * B + (b0 + ob)) * DIM + hs0 + h] = hn;
        }
        // warps 8-15 proceed straight to the next gate (part parity-safe)
    }
}

// =====================================================================
// Kernel 3: softmax over H (axis=1 of [B,H,T]) + transpose -> [b][h][t]
// =====================================================================
__global__ __launch_bounds__(256) void softmax_kernel(float* __restrict__ out)
{
    __shared__ float tile[16][513];
    __shared__ float rinv[16];

    const int tid = threadIdx.x;
    const int bb  = blockIdx.y;
    const int t0  = blockIdx.x * 16;

#pragma unroll
    for (int it = 0; it < 32; ++it) {
        int f = it * 256 + tid;
        int tt = f >> 9, hh = f & 511;
        tile[tt][hh] = __ldg(&g_hid[((size_t)(t0 + tt) * B + bb) * DIM + hh]);
    }
    __syncthreads();

    const int wid = tid >> 5, lane = tid & 31;
#pragma unroll
    for (int rr = 0; rr < 2; ++rr) {
        int tt = wid * 2 + rr;
        float m = -3.4e38f;
#pragma unroll
        for (int k = 0; k < 16; ++k) m = fmaxf(m, tile[tt][lane + 32 * k]);
#pragma unroll
        for (int off = 16; off >= 1; off >>= 1)
            m = fmaxf(m, __shfl_xor_sync(0xffffffffu, m, off));
        float s = 0.0f;
#pragma unroll
        for (int k = 0; k < 16; ++k) {
            float e = __expf(tile[tt][lane + 32 * k] - m);
            tile[tt][lane + 32 * k] = e;
            s += e;
        }
#pragma unroll
        for (int off = 16; off >= 1; off >>= 1)
            s += __shfl_xor_sync(0xffffffffu, s, off);
        if (lane == 0) rinv[tt] = 1.0f / s;
    }
    __syncthreads();

    const int hw  = tid >> 4;
    const int l16 = tid & 15;
#pragma unroll
    for (int it = 0; it < 32; ++it) {
        int hh = it * 16 + hw;
        float v = tile[l16][hh] * rinv[l16];
        out[((size_t)bb * DIM + hh) * T + t0 + l16] = v;
    }
}

// =====================================================================
extern "C" void kernel_launch(void* const* d_in, const int* in_sizes, int n_in,
                              void* d_out, int out_size)
{
    const int*   x    = (const int*)  d_in[0];
    const float* emb  = (const float*)d_in[1];
    const float* W_ih = (const float*)d_in[2];
    const float* W_hh = (const float*)d_in[3];
    const float* b_ih = (const float*)d_in[4];
    const float* b_hh = (const float*)d_in[5];
    float* out = (float*)d_out;

    void* p_flag;
    cudaGetSymbolAddress(&p_flag, g_flag);
    cudaMemsetAsync(p_flag, 0, sizeof(unsigned) * (size_t)T * 8 * 16 * 8);

    // 1) input projection GEMM -> g_xp
    gemm_xp_kernel<<<dim3(DIM / GBN, (T * B) / GBM), 256>>>(x, emb, W_ih, b_ih, b_hh);

    // 2) persistent recurrence -> g_hid
    rnn_kernel<<<dim3(RNN_SLICES, RNN_GROUPS), 512>>>(W_hh);

    // 3) softmax over H + transpose -> out
    softmax_kernel<<<dim3(T / 16, B), 256>>>(out);
}